// round 17
// baseline (speedup 1.0000x reference)
#include <cuda_runtime.h>
#include <cuda_fp16.h>
#include <cstdint>

#define NN 50000
#define EMAX 1700000
#define SCAN_B 512
#define NBK ((NN + SCAN_B - 1) / SCAN_B)   // 98

// PDL primitives: no-ops when kernel isn't launched as programmatic dependent.
#define GDC_WAIT()   asm volatile("griddepcontrol.wait;" ::: "memory")
#define GDC_LAUNCH() asm volatile("griddepcontrol.launch_dependents;" ::: "memory")

// ---------------- scratch (device globals; no allocation allowed) ----------
__device__ __half g_xwh[(size_t)NN * 512];   // fp16 GEMM out
__device__ __half g_h1h[(size_t)NN * 256];   // h1 activation, fp16
__device__ __half g_h2h[(size_t)NN * 512];   // h2 activation, fp16
__device__ __half g_h4inh[(size_t)NN * 256]; // L2 agg tmp / L3 out, fp16
__device__ float  g_dinv[NN];
__device__ int    g_degi[NN];
__device__ int    g_off[NN];
__device__ int    g_cur[NN];
__device__ int    g_bsum[NBK];
__device__ int    g_btop[NBK];
__device__ int2   g_edge[EMAX];     // packed {src, __float_as_int(nrm)}
__device__ int    g_is64;
// Pre-packed B tiles: L1 @0 (32), L2 @65536 (32), L3 @131072 (32), L4 @196608 (8)
__device__ uint32_t g_wp[212992];
__device__ uint32_t g_wpl[16384];   // L4 lo part (2-pass)

// ---------------- helpers ---------------------------------------------------
__device__ __forceinline__ uint32_t pack_f16(float a, float b) {
    __half2 v = __floats2half2_rn(a, b);
    return *reinterpret_cast<uint32_t*>(&v);
}
__device__ __forceinline__ void mma_f16(float* c, uint32_t a0, uint32_t a1,
                                        uint32_t a2, uint32_t a3,
                                        uint32_t b0, uint32_t b1) {
    asm volatile(
        "mma.sync.aligned.m16n8k16.row.col.f32.f16.f16.f32 "
        "{%0,%1,%2,%3}, {%4,%5,%6,%7}, {%8,%9}, {%0,%1,%2,%3};\n"
        : "+f"(c[0]), "+f"(c[1]), "+f"(c[2]), "+f"(c[3])
        : "r"(a0), "r"(a1), "r"(a2), "r"(a3), "r"(b0), "r"(b1));
}
__device__ __forceinline__ float elu1(float y) {
    return y > 0.f ? y : expm1f(y);
}
__device__ __forceinline__ float4 ldh4(const __half* p, int idx4) {
    uint2 u = ((const uint2*)p)[idx4];
    float2 f0 = __half22float2(*reinterpret_cast<__half2*>(&u.x));
    float2 f1 = __half22float2(*reinterpret_cast<__half2*>(&u.y));
    return make_float4(f0.x, f0.y, f1.x, f1.y);
}
__device__ __forceinline__ void sth4(__half* p, int idx4, float4 v) {
    __half2 h0 = __floats2half2_rn(v.x, v.y);
    __half2 h1 = __floats2half2_rn(v.z, v.w);
    uint2 u;
    u.x = *reinterpret_cast<uint32_t*>(&h0);
    u.y = *reinterpret_cast<uint32_t*>(&h1);
    ((uint2*)p)[idx4] = u;
}
__device__ __forceinline__ void fma_h8(uint4 u, float nrm, float4* acc) {
    const __half2* h = reinterpret_cast<const __half2*>(&u);
    float2 f;
    f = __half22float2(h[0]);
    acc[0].x = fmaf(nrm, f.x, acc[0].x); acc[0].y = fmaf(nrm, f.y, acc[0].y);
    f = __half22float2(h[1]);
    acc[0].z = fmaf(nrm, f.x, acc[0].z); acc[0].w = fmaf(nrm, f.y, acc[0].w);
    f = __half22float2(h[2]);
    acc[1].x = fmaf(nrm, f.x, acc[1].x); acc[1].y = fmaf(nrm, f.y, acc[1].y);
    f = __half22float2(h[3]);
    acc[1].z = fmaf(nrm, f.x, acc[1].z); acc[1].w = fmaf(nrm, f.y, acc[1].w);
}
__device__ __forceinline__ void fma_h4(float4 v, float nrm, float4* acc) {
    acc[0].x = fmaf(nrm, v.x, acc[0].x);
    acc[0].y = fmaf(nrm, v.y, acc[0].y);
    acc[0].z = fmaf(nrm, v.z, acc[0].z);
    acc[0].w = fmaf(nrm, v.w, acc[0].w);
}

// ---------------- edge-format detect ---------------------------------------
__global__ void detect_k(const unsigned int* __restrict__ e) {
    __shared__ int ok;
    if (threadIdx.x == 0) ok = 1;
    __syncthreads();
    for (int i = threadIdx.x; i < 512; i += blockDim.x)
        if (e[2 * i + 1] != 0u) ok = 0;
    __syncthreads();
    if (threadIdx.x == 0) g_is64 = ok;
}

// ---------------- CSR build -------------------------------------------------
__global__ void zero_deg_k() {
    int i = blockIdx.x * blockDim.x + threadIdx.x;
    if (i < NN) g_degi[i] = 0;
}
__global__ void hist_k(const unsigned int* __restrict__ e, long long E) {
    long long i = (long long)blockIdx.x * blockDim.x + threadIdx.x;
    if (i >= E) return;
    int d = g_is64 ? (int)e[2 * (E + i)] : (int)e[E + i];
    atomicAdd(&g_degi[d], 1);
}
__global__ void dinv_k() {
    int i = blockIdx.x * blockDim.x + threadIdx.x;
    if (i < NN) g_dinv[i] = rsqrtf((float)g_degi[i] + 1.0f);
}
__global__ void scan1_k() {
    __shared__ int sh[SCAN_B];
    int i = blockIdx.x * SCAN_B + threadIdx.x;
    int v = (i < NN) ? g_degi[i] : 0;
    sh[threadIdx.x] = v;
    __syncthreads();
#pragma unroll
    for (int o = 1; o < SCAN_B; o <<= 1) {
        int t = (threadIdx.x >= o) ? sh[threadIdx.x - o] : 0;
        __syncthreads();
        sh[threadIdx.x] += t;
        __syncthreads();
    }
    if (i < NN) g_off[i] = sh[threadIdx.x] - v;
    if (threadIdx.x == SCAN_B - 1) g_bsum[blockIdx.x] = sh[SCAN_B - 1];
}
__global__ void scan2_k() {
    if (threadIdx.x == 0) {
        int acc = 0;
        for (int b = 0; b < NBK; b++) { int t = g_bsum[b]; g_btop[b] = acc; acc += t; }
    }
}
__global__ void scan3_k() {
    int i = blockIdx.x * blockDim.x + threadIdx.x;
    if (i < NN) {
        int o = g_off[i] + g_btop[i / SCAN_B];
        g_off[i] = o;
        g_cur[i] = o;
    }
}
__global__ void fill_k(const unsigned int* __restrict__ e, long long E) {
    long long i = (long long)blockIdx.x * blockDim.x + threadIdx.x;
    if (i >= E) return;
    int s, d;
    if (g_is64) { s = (int)e[2 * i]; d = (int)e[2 * (E + i)]; }
    else        { s = (int)e[i];     d = (int)e[E + i]; }
    int pos = atomicAdd(&g_cur[d], 1);
    float nrm = g_dinv[s] * g_dinv[d];
    g_edge[pos] = make_int2(s, __float_as_int(nrm));
}

// ---------------- weight pre-pack into GEMM smem image -----------------------
__global__ void wpack_k(const float* __restrict__ W, int Kd, int Nd,
                        uint32_t* __restrict__ dst, int lo_mode) {
    int id = blockIdx.x * blockDim.x + threadIdx.x;
    if (id >= Nd * (Kd >> 1)) return;
    int n = id % Nd;
    int kh = id / Nd;
    int k = kh * 2;
    float w0 = W[(size_t)k * Nd + n];
    float w1 = W[(size_t)(k + 1) * Nd + n];
    if (lo_mode) {
        w0 = w0 - __half2float(__float2half_rn(w0));
        w1 = w1 - __half2float(__float2half_rn(w1));
    }
    int c = n >> 7, nl = n & 127;
    int kc = k >> 5, kl = k & 31;
    int ks = kl >> 4, kk = kl & 15;
    int tt = (kk >> 1) & 3, reg = kk >> 3;
    int pidx = (nl * 4 + tt) * 4 + ks * 2 + reg;
    dst[(size_t)(c * (Kd >> 5) + kc) * 2048 + pidx] = pack_f16(w0, w1);
}

// ---------------- FP16 tensor-core GEMM, double-buffered, prepacked B -------
template<bool OUTH, bool TWOPASS, bool AH>
__global__ __launch_bounds__(256) void gemm_f16_k(
    const void* __restrict__ Av,
    const uint32_t* __restrict__ Bp, const uint32_t* __restrict__ Bpl,
    void* __restrict__ Cv, int M, int Nn, int K)
{
    extern __shared__ uint32_t dsm[];
    constexpr int STG = TWOPASS ? 6144 : 4096;

    GDC_WAIT();

    int tid = threadIdx.x;
    int lane = tid & 31;
    int warp = tid >> 5;
    int g = lane >> 2;
    int t = lane & 3;
    int wm = warp & 1;
    int wn = warp >> 1;
    int rowBase = blockIdx.y * 128;
    int colBase = blockIdx.x * 128;
    int nch = K >> 5;

    float acc[4][4][4];
#pragma unroll
    for (int i = 0; i < 4; i++)
#pragma unroll
        for (int j = 0; j < 4; j++)
#pragma unroll
            for (int q = 0; q < 4; q++) acc[i][j][q] = 0.0f;

    float4 stA[4];
    uint2  stB[4], stBl[4];

    auto ldg = [&](int c) {
        int k0 = c << 5;
#pragma unroll
        for (int i = 0; i < 4; i++) {
            int idx = tid + i * 256;
            int row = idx >> 3, c4 = idx & 7;
            int gr = rowBase + row;
            if (gr < M) {
                if (AH) stA[i] = ldh4((const __half*)Av + (size_t)gr * K + k0, c4);
                else    stA[i] = *(const float4*)&((const float*)Av)[(size_t)gr * K + k0 + c4 * 4];
            } else {
                stA[i] = make_float4(0.f, 0.f, 0.f, 0.f);
            }
        }
        size_t tb = (size_t)(blockIdx.x * nch + c) * 1024;
        const uint2* bp2 = (const uint2*)Bp + tb;
#pragma unroll
        for (int w = 0; w < 4; w++) stB[w] = bp2[tid + w * 256];
        if (TWOPASS) {
            const uint2* bl2 = (const uint2*)Bpl + tb;
#pragma unroll
            for (int w = 0; w < 4; w++) stBl[w] = bl2[tid + w * 256];
        }
    };
    auto sts = [&](int s) {
        uint32_t* A0 = dsm + s * STG;
        uint2* B0 = (uint2*)(A0 + 2048);
#pragma unroll
        for (int i = 0; i < 4; i++) {
            int idx = tid + i * 256;
            int row = idx >> 3, c4 = idx & 7;
            int c = c4 * 4;
            int mt = row >> 4, rr = row & 15;
            int gg = rr & 7, h = rr >> 3;
            int ks = c >> 4, kk = c & 15;
            int khalf = kk >> 3;
            int t0 = (kk & 7) >> 1;
            int reg = h + 2 * khalf;
            int base = ((ks * 8 + mt) * 8 + gg) * 16 + reg;
            A0[base + t0 * 4]       = pack_f16(stA[i].x, stA[i].y);
            A0[base + (t0 + 1) * 4] = pack_f16(stA[i].z, stA[i].w);
        }
#pragma unroll
        for (int w = 0; w < 4; w++) B0[tid + w * 256] = stB[w];
        if (TWOPASS) {
            uint2* B1 = (uint2*)(A0 + 4096);
#pragma unroll
            for (int w = 0; w < 4; w++) B1[tid + w * 256] = stBl[w];
        }
    };
    auto comp = [&](int s) {
        uint32_t* A0 = dsm + s * STG;
        uint32_t* B0 = A0 + 2048;
        uint4 bh[4];
#pragma unroll
        for (int j = 0; j < 4; j++)
            bh[j] = *(uint4*)&B0[(((wn * 4 + j) * 8 + g) * 4 + t) * 4];
#pragma unroll
        for (int ks = 0; ks < 2; ks++) {
            uint4 ah[4];
#pragma unroll
            for (int i = 0; i < 4; i++)
                ah[i] = *(uint4*)&A0[((ks * 8 + wm * 4 + i) * 8 + g) * 16 + t * 4];
#pragma unroll
            for (int i = 0; i < 4; i++)
#pragma unroll
                for (int j = 0; j < 4; j++) {
                    uint32_t b0 = ks ? bh[j].z : bh[j].x;
                    uint32_t b1 = ks ? bh[j].w : bh[j].y;
                    mma_f16(acc[i][j], ah[i].x, ah[i].y, ah[i].z, ah[i].w, b0, b1);
                }
            if (TWOPASS) {
                uint32_t* B1 = A0 + 4096;
#pragma unroll
                for (int j = 0; j < 4; j++) {
                    uint4 bl = *(uint4*)&B1[(((wn * 4 + j) * 8 + g) * 4 + t) * 4];
                    uint32_t b0 = ks ? bl.z : bl.x;
                    uint32_t b1 = ks ? bl.w : bl.y;
#pragma unroll
                    for (int i = 0; i < 4; i++)
                        mma_f16(acc[i][j], ah[i].x, ah[i].y, ah[i].z, ah[i].w, b0, b1);
                }
            }
        }
    };

    ldg(0);
    sts(0);
    __syncthreads();
    for (int c = 0; c < nch; c++) {
        int cur = c & 1;
        if (c + 1 < nch) ldg(c + 1);
        comp(cur);
        if (c + 1 < nch) sts(cur ^ 1);
        __syncthreads();
    }

#pragma unroll
    for (int i = 0; i < 4; i++) {
        int r0 = rowBase + wm * 64 + i * 16 + g;
        int r1 = r0 + 8;
#pragma unroll
        for (int j = 0; j < 4; j++) {
            int col = colBase + wn * 32 + j * 8 + t * 2;
            if (OUTH) {
                __half* C = (__half*)Cv;
                if (r0 < M) *(__half2*)&C[(size_t)r0 * Nn + col] =
                    __floats2half2_rn(acc[i][j][0], acc[i][j][1]);
                if (r1 < M) *(__half2*)&C[(size_t)r1 * Nn + col] =
                    __floats2half2_rn(acc[i][j][2], acc[i][j][3]);
            } else {
                float* C = (float*)Cv;
                if (r0 < M) *(float2*)&C[(size_t)r0 * Nn + col] =
                    make_float2(acc[i][j][0], acc[i][j][1]);
                if (r1 < M) *(float2*)&C[(size_t)r1 * Nn + col] =
                    make_float2(acc[i][j][2], acc[i][j][3]);
            }
        }
    }
    GDC_LAUNCH();
}

// ---------------- fused warp-per-node agg (fp16 in) + LN + ELU --------------
template<int F, bool OUTH>
__global__ __launch_bounds__(256) void agg_ln_elu_k(
    const __half* __restrict__ xw,
    const float* __restrict__ bias,
    const float* __restrict__ gamma,
    const float* __restrict__ beta,
    void* __restrict__ outv,
    const __half* __restrict__ resid,
    float* __restrict__ out_raw,
    float* __restrict__ out_bn,
    const float* __restrict__ wc,
    const float* __restrict__ bcp,
    float* __restrict__ logits)
{
    constexpr int RF = F / 128;
    GDC_WAIT();
    int warp = (blockIdx.x * blockDim.x + threadIdx.x) >> 5;
    int lane = threadIdx.x & 31;
    if (warp >= NN) { GDC_LAUNCH(); return; }
    int d = warp;

    float4 acc[RF];
#pragma unroll
    for (int i = 0; i < RF; i++) acc[i] = make_float4(0.f, 0.f, 0.f, 0.f);

    int beg = g_off[d];
    int cnt = g_degi[d];

    for (int b0 = 0; b0 < cnt; b0 += 32) {
        int n = min(32, cnt - b0);
        int2 rec = make_int2(0, 0);
        if (lane < n) rec = g_edge[beg + b0 + lane];
        int j = 0;
        for (; j + 3 < n; j += 4) {
            int   s0 = __shfl_sync(0xffffffffu, rec.x, j);
            float n0 = __int_as_float(__shfl_sync(0xffffffffu, rec.y, j));
            int   s1 = __shfl_sync(0xffffffffu, rec.x, j + 1);
            float n1 = __int_as_float(__shfl_sync(0xffffffffu, rec.y, j + 1));
            int   s2 = __shfl_sync(0xffffffffu, rec.x, j + 2);
            float n2 = __int_as_float(__shfl_sync(0xffffffffu, rec.y, j + 2));
            int   s3 = __shfl_sync(0xffffffffu, rec.x, j + 3);
            float n3 = __int_as_float(__shfl_sync(0xffffffffu, rec.y, j + 3));
            if (F == 256) {
                uint4 u0 = ((const uint4*)(xw + (size_t)s0 * F))[lane];
                uint4 u1 = ((const uint4*)(xw + (size_t)s1 * F))[lane];
                uint4 u2 = ((const uint4*)(xw + (size_t)s2 * F))[lane];
                uint4 u3 = ((const uint4*)(xw + (size_t)s3 * F))[lane];
                fma_h8(u0, n0, acc); fma_h8(u1, n1, acc);
                fma_h8(u2, n2, acc); fma_h8(u3, n3, acc);
            } else {
                float4 v0 = ldh4(xw + (size_t)s0 * F, lane);
                float4 v1 = ldh4(xw + (size_t)s1 * F, lane);
                float4 v2 = ldh4(xw + (size_t)s2 * F, lane);
                float4 v3 = ldh4(xw + (size_t)s3 * F, lane);
                fma_h4(v0, n0, acc); fma_h4(v1, n1, acc);
                fma_h4(v2, n2, acc); fma_h4(v3, n3, acc);
            }
        }
        for (; j < n; j++) {
            int   s0 = __shfl_sync(0xffffffffu, rec.x, j);
            float n0 = __int_as_float(__shfl_sync(0xffffffffu, rec.y, j));
            if (F == 256) {
                uint4 u0 = ((const uint4*)(xw + (size_t)s0 * F))[lane];
                fma_h8(u0, n0, acc);
            } else {
                float4 v0 = ldh4(xw + (size_t)s0 * F, lane);
                fma_h4(v0, n0, acc);
            }
        }
    }

    auto fidx = [&](int i) { return (F == 256) ? (lane * 2 + i) : lane; };
    {
        float dd = g_dinv[d];
        float nrm = dd * dd;
        if (F == 256) {
            uint4 u = ((const uint4*)(xw + (size_t)d * F))[lane];
            fma_h8(u, nrm, acc);
        } else {
            float4 v = ldh4(xw + (size_t)d * F, lane);
            fma_h4(v, nrm, acc);
        }
        const float4* bb = (const float4*)bias;
#pragma unroll
        for (int i = 0; i < RF; i++) {
            float4 b = bb[fidx(i)];
            acc[i].x += b.x; acc[i].y += b.y; acc[i].z += b.z; acc[i].w += b.w;
        }
    }

    float s = 0.f, q = 0.f;
#pragma unroll
    for (int i = 0; i < RF; i++) {
        s += acc[i].x + acc[i].y + acc[i].z + acc[i].w;
        q += acc[i].x * acc[i].x + acc[i].y * acc[i].y
           + acc[i].z * acc[i].z + acc[i].w * acc[i].w;
    }
#pragma unroll
    for (int o = 16; o > 0; o >>= 1) {
        s += __shfl_xor_sync(0xffffffffu, s, o);
        q += __shfl_xor_sync(0xffffffffu, q, o);
    }
    constexpr float invF = 1.0f / F;
    float mu = s * invF;
    float var = q * invF - mu * mu;
    float rstd = rsqrtf(var + 1e-5f);

    const float4* gp = (const float4*)gamma;
    const float4* bp = (const float4*)beta;
    float4* rawp = out_raw ? (float4*)(out_raw + (size_t)d * F) : nullptr;
    float4* bnp  = out_bn  ? (float4*)(out_bn  + (size_t)d * F) : nullptr;

    float4 eo_last;
#pragma unroll
    for (int i = 0; i < RF; i++) {
        int idx = fidx(i);
        float4 gv = gp[idx];
        float4 bv = bp[idx];
        float4 y;
        y.x = (acc[i].x - mu) * rstd * gv.x + bv.x;
        y.y = (acc[i].y - mu) * rstd * gv.y + bv.y;
        y.z = (acc[i].z - mu) * rstd * gv.z + bv.z;
        y.w = (acc[i].w - mu) * rstd * gv.w + bv.w;
        if (rawp) rawp[idx] = acc[i];
        if (bnp)  bnp[idx]  = y;
        float4 eo = make_float4(elu1(y.x), elu1(y.y), elu1(y.z), elu1(y.w));
        if (resid) {
            float4 r = ldh4(resid + (size_t)d * F, idx);
            eo.x += r.x; eo.y += r.y; eo.z += r.z; eo.w += r.w;
        }
        if (outv) {
            if (OUTH) sth4((__half*)outv + (size_t)d * F, idx, eo);
            else ((float4*)((float*)outv + (size_t)d * F))[idx] = eo;
        }
        eo_last = eo;
    }

    if (RF == 1 && wc) {
        const float4* wrow = (const float4*)wc;
        float4 w0 = wrow[lane * 4 + 0];
        float4 w1 = wrow[lane * 4 + 1];
        float4 w2 = wrow[lane * 4 + 2];
        float4 w3 = wrow[lane * 4 + 3];
        float c0 = eo_last.x * w0.x + eo_last.y * w1.x + eo_last.z * w2.x + eo_last.w * w3.x;
        float c1 = eo_last.x * w0.y + eo_last.y * w1.y + eo_last.z * w2.y + eo_last.w * w3.y;
        float c2 = eo_last.x * w0.z + eo_last.y * w1.z + eo_last.z * w2.z + eo_last.w * w3.z;
        float c3 = eo_last.x * w0.w + eo_last.y * w1.w + eo_last.z * w2.w + eo_last.w * w3.w;
#pragma unroll
        for (int o = 16; o > 0; o >>= 1) {
            c0 += __shfl_down_sync(0xffffffffu, c0, o);
            c1 += __shfl_down_sync(0xffffffffu, c1, o);
            c2 += __shfl_down_sync(0xffffffffu, c2, o);
            c3 += __shfl_down_sync(0xffffffffu, c3, o);
        }
        if (lane == 0) {
            *(float4*)&logits[(size_t)d * 4] = make_float4(
                c0 + bcp[0], c1 + bcp[1], c2 + bcp[2], c3 + bcp[3]);
        }
    }
    GDC_LAUNCH();
}

// ---------------- gather-only aggregation (fp16 in, fp16 out), F=256 --------
__global__ __launch_bounds__(256) void agg_only256_k(
    const __half* __restrict__ in, __half* __restrict__ out)
{
    GDC_WAIT();
    int warp = (blockIdx.x * blockDim.x + threadIdx.x) >> 5;
    int lane = threadIdx.x & 31;
    if (warp >= NN) { GDC_LAUNCH(); return; }
    int d = warp;

    float4 acc[2];
    acc[0] = make_float4(0.f, 0.f, 0.f, 0.f);
    acc[1] = make_float4(0.f, 0.f, 0.f, 0.f);

    int beg = g_off[d];
    int cnt = g_degi[d];

    for (int b0 = 0; b0 < cnt; b0 += 32) {
        int n = min(32, cnt - b0);
        int2 rec = make_int2(0, 0);
        if (lane < n) rec = g_edge[beg + b0 + lane];
        int j = 0;
        for (; j + 3 < n; j += 4) {
            int   s0 = __shfl_sync(0xffffffffu, rec.x, j);
            float n0 = __int_as_float(__shfl_sync(0xffffffffu, rec.y, j));
            int   s1 = __shfl_sync(0xffffffffu, rec.x, j + 1);
            float n1 = __int_as_float(__shfl_sync(0xffffffffu, rec.y, j + 1));
            int   s2 = __shfl_sync(0xffffffffu, rec.x, j + 2);
            float n2 = __int_as_float(__shfl_sync(0xffffffffu, rec.y, j + 2));
            int   s3 = __shfl_sync(0xffffffffu, rec.x, j + 3);
            float n3 = __int_as_float(__shfl_sync(0xffffffffu, rec.y, j + 3));
            uint4 u0 = ((const uint4*)(in + (size_t)s0 * 256))[lane];
            uint4 u1 = ((const uint4*)(in + (size_t)s1 * 256))[lane];
            uint4 u2 = ((const uint4*)(in + (size_t)s2 * 256))[lane];
            uint4 u3 = ((const uint4*)(in + (size_t)s3 * 256))[lane];
            fma_h8(u0, n0, acc); fma_h8(u1, n1, acc);
            fma_h8(u2, n2, acc); fma_h8(u3, n3, acc);
        }
        for (; j < n; j++) {
            int   s0 = __shfl_sync(0xffffffffu, rec.x, j);
            float n0 = __int_as_float(__shfl_sync(0xffffffffu, rec.y, j));
            uint4 u0 = ((const uint4*)(in + (size_t)s0 * 256))[lane];
            fma_h8(u0, n0, acc);
        }
    }

    {
        float dd = g_dinv[d];
        float nrm = dd * dd;
        uint4 u = ((const uint4*)(in + (size_t)d * 256))[lane];
        fma_h8(u, nrm, acc);
    }

    __half* op = out + (size_t)d * 256;
    sth4(op, lane * 2, acc[0]);
    sth4(op, lane * 2 + 1, acc[1]);
    GDC_LAUNCH();
}

// ---------------- standalone bias + LN + ELU (fp16 in, fp16 out) ------------
template<int F>
__global__ void ln_elu_h_k(const __half* __restrict__ in,
                           const float* __restrict__ bias,
                           const float* __restrict__ gamma,
                           const float* __restrict__ beta,
                           __half* __restrict__ out)
{
    GDC_WAIT();
    int node = blockIdx.x;
    int tid = threadIdx.x;
    constexpr int NT = F / 4;
    constexpr int NW = NT / 32;
    float4 v = ldh4(in + (size_t)node * F, tid);
    float4 bb = ((const float4*)bias)[tid];
    v.x += bb.x; v.y += bb.y; v.z += bb.z; v.w += bb.w;
    float s = v.x + v.y + v.z + v.w;
    float q = v.x * v.x + v.y * v.y + v.z * v.z + v.w * v.w;
#pragma unroll
    for (int o = 16; o > 0; o >>= 1) {
        s += __shfl_xor_sync(0xffffffffu, s, o);
        q += __shfl_xor_sync(0xffffffffu, q, o);
    }
    __shared__ float ss[NW], sq[NW];
    int wid = tid >> 5, lane = tid & 31;
    if (NW > 1) {
        if (lane == 0) { ss[wid] = s; sq[wid] = q; }
        __syncthreads();
        s = 0.f; q = 0.f;
#pragma unroll
        for (int w = 0; w < NW; w++) { s += ss[w]; q += sq[w]; }
    }
    constexpr float invF = 1.0f / F;
    float mu = s * invF;
    float var = q * invF - mu * mu;
    float rstd = rsqrtf(var + 1e-5f);
    float4 gv = ((const float4*)gamma)[tid];
    float4 bv = ((const float4*)beta)[tid];
    float4 y;
    y.x = (v.x - mu) * rstd * gv.x + bv.x;
    y.y = (v.y - mu) * rstd * gv.y + bv.y;
    y.z = (v.z - mu) * rstd * gv.z + bv.z;
    y.w = (v.w - mu) * rstd * gv.w + bv.w;
    float4 eo = make_float4(elu1(y.x), elu1(y.y), elu1(y.z), elu1(y.w));
    sth4(out + (size_t)node * F, tid, eo);
    GDC_LAUNCH();
}

// ---------------- host launch ----------------------------------------------
static inline void* sym(const void* s) {
    void* p = nullptr;
    cudaGetSymbolAddress(&p, s);
    return p;
}

// launch helper with Programmatic Stream Serialization on stream 0
template<typename Fn, typename... Args>
static inline void launch_pdl(Fn fn, dim3 grid, dim3 block, size_t smem,
                              Args... args) {
    cudaLaunchAttribute at[1];
    at[0].id = cudaLaunchAttributeProgrammaticStreamSerialization;
    at[0].val.programmaticStreamSerializationAllowed = 1;
    cudaLaunchConfig_t cfg{};
    cfg.gridDim = grid;
    cfg.blockDim = block;
    cfg.dynamicSmemBytes = smem;
    cfg.stream = 0;
    cfg.attrs = at;
    cfg.numAttrs = 1;
    cudaLaunchKernelEx(&cfg, fn, args...);
}

extern "C" void kernel_launch(void* const* d_in, const int* in_sizes, int n_in,
                              void* d_out, int out_size) {
    const float* x  = (const float*)d_in[0];
    const unsigned int* e = (const unsigned int*)d_in[1];
    const float* W1 = (const float*)d_in[2];  const float* b1 = (const float*)d_in[3];
    const float* W2 = (const float*)d_in[4];  const float* b2 = (const float*)d_in[5];
    const float* W3 = (const float*)d_in[6];  const float* b3 = (const float*)d_in[7];
    const float* W4 = (const float*)d_in[8];  const float* b4 = (const float*)d_in[9];
    const float* Wc = (const float*)d_in[10]; const float* bc = (const float*)d_in[11];
    const float* g1 = (const float*)d_in[12]; const float* be1 = (const float*)d_in[13];
    const float* g2 = (const float*)d_in[14]; const float* be2 = (const float*)d_in[15];
    const float* g3 = (const float*)d_in[16]; const float* be3 = (const float*)d_in[17];
    const float* g4 = (const float*)d_in[18]; const float* be4 = (const float*)d_in[19];

    long long E = (long long)in_sizes[1] / 2;

    float* out        = (float*)d_out;
    float* out_logits = out;
    float* out_conv   = out + (size_t)NN * 4;
    float* out_bn     = out_conv + (size_t)NN * 128;

    __half* xwh   = (__half*)sym(g_xwh);
    __half* h1h   = (__half*)sym(g_h1h);
    __half* h2h   = (__half*)sym(g_h2h);
    __half* h4inh = (__half*)sym(g_h4inh);
    uint32_t* wp  = (uint32_t*)sym(g_wp);
    uint32_t* wpl = (uint32_t*)sym(g_wpl);

    static cudaStream_t s2 = nullptr;
    static cudaEvent_t ev1 = nullptr, ev2 = nullptr;
    if (s2 == nullptr) {
        cudaStreamCreateWithFlags(&s2, cudaStreamNonBlocking);
        cudaEventCreateWithFlags(&ev1, cudaEventDisableTiming);
        cudaEventCreateWithFlags(&ev2, cudaEventDisableTiming);
        cudaFuncSetAttribute(gemm_f16_k<true, false, false>,
                             cudaFuncAttributeMaxDynamicSharedMemorySize, 32768);
        cudaFuncSetAttribute(gemm_f16_k<true, false, true>,
                             cudaFuncAttributeMaxDynamicSharedMemorySize, 32768);
        cudaFuncSetAttribute(gemm_f16_k<true, true, true>,
                             cudaFuncAttributeMaxDynamicSharedMemorySize, 49152);
    }

    int mgrid = (NN + 127) / 128;   // 391
    unsigned agg_blocks = (NN * 32 + 255) / 256;

    // ---- fork: CSR build + W2 pack on s2, overlapped with main-stream work --
    cudaEventRecord(ev1, 0);
    cudaStreamWaitEvent(s2, ev1, 0);

    detect_k<<<1, 256, 0, s2>>>(e);
    zero_deg_k<<<(NN + 255) / 256, 256, 0, s2>>>();
    hist_k<<<(unsigned)((E + 255) / 256), 256, 0, s2>>>(e, E);
    dinv_k<<<(NN + 255) / 256, 256, 0, s2>>>();
    scan1_k<<<NBK, SCAN_B, 0, s2>>>();
    scan2_k<<<1, 32, 0, s2>>>();
    scan3_k<<<(NN + 255) / 256, 256, 0, s2>>>();
    fill_k<<<(unsigned)((E + 255) / 256), 256, 0, s2>>>(e, E);
    wpack_k<<<(512 * 128 + 255) / 256, 256, 0, s2>>>(W2, 256, 512, wp + 65536, 0);
    cudaEventRecord(ev2, s2);

    // main stream: W1/W3/W4 packs + layer-1 GEMM, concurrent with s2
    wpack_k<<<(256 * 256 + 255) / 256, 256>>>(W1, 512, 256, wp, 0);
    gemm_f16_k<true, false, false><<<dim3(2, mgrid), 256, 32768>>>(
        x, wp, nullptr, xwh, NN, 256, 512);
    wpack_k<<<(256 * 256 + 255) / 256, 256>>>(W3, 512, 256, wp + 131072, 0);
    wpack_k<<<(128 * 128 + 255) / 256, 256>>>(W4, 256, 128, wp + 196608, 0);
    wpack_k<<<(128 * 128 + 255) / 256, 256>>>(W4, 256, 128, wpl, 1);

    cudaStreamWaitEvent(0, ev2, 0);

    // ---- post-join dependent chain: PDL launches ----
    // layer 1: agg + LN + ELU -> h1 (fp16)
    launch_pdl(agg_ln_elu_k<256, true>, dim3(agg_blocks), dim3(256), 0,
               (const __half*)xwh, b1, g1, be1, (void*)h1h,
               (const __half*)nullptr, (float*)nullptr, (float*)nullptr,
               (const float*)nullptr, (const float*)nullptr, (float*)nullptr);

    // layer 2 (agg-first): h4in = A_hat h1; gemm -> fp16; LN -> h2
    launch_pdl(agg_only256_k, dim3(agg_blocks), dim3(256), 0,
               (const __half*)h1h, h4inh);
    launch_pdl(gemm_f16_k<true, false, true>, dim3(4, mgrid), dim3(256), 32768,
               (const void*)h4inh, (const uint32_t*)(wp + 65536),
               (const uint32_t*)nullptr, (void*)xwh, NN, 512, 256);
    launch_pdl(ln_elu_h_k<512>, dim3(NN), dim3(128), 0,
               (const __half*)xwh, b2, g2, be2, h2h);

    // layer 3: gemm(h2)@W3 -> fp16; agg + LN + ELU + resid(h1) -> h4in
    launch_pdl(gemm_f16_k<true, false, true>, dim3(2, mgrid), dim3(256), 32768,
               (const void*)h2h, (const uint32_t*)(wp + 131072),
               (const uint32_t*)nullptr, (void*)xwh, NN, 256, 512);
    launch_pdl(agg_ln_elu_k<256, true>, dim3(agg_blocks), dim3(256), 0,
               (const __half*)xwh, b3, g3, be3, (void*)h4inh,
               (const __half*)h1h, (float*)nullptr, (float*)nullptr,
               (const float*)nullptr, (const float*)nullptr, (float*)nullptr);

    // layer 4: gemm (2-pass, exact weights) -> fp16; agg + LN + classifier
    launch_pdl(gemm_f16_k<true, true, true>, dim3(1, mgrid), dim3(256), 49152,
               (const void*)h4inh, (const uint32_t*)(wp + 196608),
               (const uint32_t*)wpl, (void*)xwh, NN, 128, 256);
    launch_pdl(agg_ln_elu_k<128, false>, dim3(agg_blocks), dim3(256), 0,
               (const __half*)xwh, b4, g4, be4, (void*)nullptr,
               (const __half*)nullptr, out_conv, out_bn, Wc, bc, out_logits);
}